// round 4
// baseline (speedup 1.0000x reference)
#include <cuda_runtime.h>
#include <cstdint>
#include <float.h>
#include <math.h>

#define B   64
#define Q   32
#define KD  100
#define BQ  (B*Q)              // 2048 rows (i,q)
#define ROWLEN  (B*KD)         // 6400 elems per softmax row
#define ROWLEN4 (ROWLEN/4)     // 1600 float4
#define TEMP 0.07f
#define EMA  0.99f

#define N_OUT   ((size_t)B*B*Q*KD)   // 13107200
#define N_CONF  ((size_t)30000*Q*KD) // 96000000
#define N_MASK  ((size_t)B*Q*KD)     // 204800

__device__ float g_logZ[BQ];
__device__ int   g_harg[BQ];
__device__ int   g_bidx[B];
__device__ int   g_mask_w;   // 1=u8, 4=i32, 8=i64, 5=f32, 9=f64
__device__ int   g_topk;
__device__ float g_loss_num;
__device__ float g_phrase_cnt;

__device__ __forceinline__ bool mask_at(const unsigned char* xm, size_t idx) {
    const int w = g_mask_w;
    if (w == 1) return xm[idx] != 0;
    if (w == 4) return ((const int*)xm)[idx] != 0;
    if (w == 8) return ((const long long*)xm)[idx] != 0;
    if (w == 5) return ((const float*)xm)[idx] != 0.f;
    return ((const double*)xm)[idx] != 0.0;
}

// Single-thread setup: accumulator reset + dtype-width detection for
// x_mask / batch_index / topk. All probe reads stay within the smallest
// possible buffer size for each input.
__global__ void k_init(const unsigned char* __restrict__ xm,
                       const int* __restrict__ braw,
                       const int* __restrict__ traw, int has_topk) {
    g_loss_num = 0.f; g_phrase_cnt = 0.f;

    // ---- x_mask width (probe first 256 logical elements; <=2048 bytes) ----
    {
        const int S = 256;
        bool ok8 = true, ok4 = true;
        for (int e = 0; e < S && ok8; ++e) {
            const unsigned char* p = xm + 8*e;
            if (p[0] > 1) ok8 = false;
            for (int j = 1; j < 8; ++j) if (p[j] != 0) { ok8 = false; break; }
        }
        for (int e = 0; e < S && ok4; ++e) {
            const unsigned char* p = xm + 4*e;
            if (p[0] > 1 || p[1] != 0 || p[2] != 0 || p[3] != 0) ok4 = false;
        }
        if (ok8)      g_mask_w = 8;
        else if (ok4) g_mask_w = 4;
        else {
            bool okd = true, okf = true;
            const double* pd = (const double*)xm;
            const float*  pf = (const float*)xm;
            for (int e = 0; e < S && okd; ++e) { double d = pd[e]; if (d != 0.0 && d != 1.0) okd = false; }
            for (int e = 0; e < S && okf; ++e) { float  f = pf[e]; if (f != 0.f && f != 1.f) okf = false; }
            if (okd)      g_mask_w = 9;
            else if (okf) g_mask_w = 5;
            else          g_mask_w = 1;
        }
    }

    // ---- batch_index dtype (probe first 256 bytes only) ----
    {
        bool ok64 = true;
        for (int i = 0; i < 32; ++i) {
            if (braw[2*i+1] != 0) { ok64 = false; break; }
            if (braw[2*i] < 0 || braw[2*i] >= 30000) { ok64 = false; break; }
        }
        bool ok32 = true;
        if (!ok64) {
            for (int i = 0; i < B; ++i)
                if (braw[i] < 0 || braw[i] >= 30000) { ok32 = false; break; }
        }
        if (ok64)      { for (int i = 0; i < B; ++i) g_bidx[i] = (int)((const long long*)braw)[i]; }
        else if (ok32) { for (int i = 0; i < B; ++i) g_bidx[i] = braw[i]; }
        else {
            bool okf = true;
            const float* pf = (const float*)braw;
            for (int i = 0; i < B; ++i) {
                float f = pf[i];
                if (!(f >= 0.f && f < 30000.f) || f != floorf(f)) { okf = false; break; }
            }
            if (okf) { for (int i = 0; i < B; ++i) g_bidx[i] = (int)pf[i]; }
            else     { const double* pd = (const double*)braw;
                       for (int i = 0; i < B; ++i) g_bidx[i] = (int)pd[i]; }
        }
    }

    // ---- topk value ----
    {
        int v = 3;
        if (has_topk) {
            int vi = traw[0];                       // i32 or i64 low word
            if (vi >= 1 && vi <= KD) v = vi;
            else {
                float vf = ((const float*)traw)[0];
                if (vf >= 1.f && vf <= (float)KD) v = (int)vf;
                // f64 needs 8 bytes; only read if i32/f32 both implausible
                else {
                    double vd = ((const double*)traw)[0];
                    if (vd >= 1.0 && vd <= (double)KD) v = (int)vd;
                }
            }
        }
        if (v > KD) v = KD;
        if (v < 0)  v = 0;
        g_topk = v;
    }
}

// One block per (i,q): load the 6400-element slice into smem (float4 loads),
// logsumexp, write atten = x/T - logZ with coalesced scalar stores
// (atten base is only 4B-aligned: it sits at out+1 after the loss scalar).
__global__ void k_softmax(const float* __restrict__ outp, float* __restrict__ atten) {
    const int r = blockIdx.x;            // 0..2047
    const int i = r / Q, qq = r % Q;
    __shared__ float sv[ROWLEN];
    __shared__ float red[256];
    const int t = threadIdx.x;
    const size_t base = (size_t)i * B * Q * KD + (size_t)qq * KD;

    float mx = -FLT_MAX;
    for (int f = t; f < ROWLEN4; f += 256) {
        const int e  = 4 * f;
        const int j  = e / KD;
        const int kk = e % KD;          // KD%4==0 -> all 4 lanes same j, contiguous
        float4 v = *(const float4*)(outp + base + (size_t)j * Q * KD + kk);
        v.x /= TEMP; v.y /= TEMP; v.z /= TEMP; v.w /= TEMP;
        *(float4*)(sv + e) = v;
        mx = fmaxf(mx, fmaxf(fmaxf(v.x, v.y), fmaxf(v.z, v.w)));
    }
    red[t] = mx; __syncthreads();
    for (int s = 128; s > 0; s >>= 1) { if (t < s) red[t] = fmaxf(red[t], red[t+s]); __syncthreads(); }
    mx = red[0]; __syncthreads();

    float sum = 0.f;
    for (int e = t; e < ROWLEN; e += 256) {
        sum += expf(sv[e] - mx);
    }
    red[t] = sum; __syncthreads();
    for (int s = 128; s > 0; s >>= 1) { if (t < s) red[t] += red[t+s]; __syncthreads(); }
    const float logZ = mx + logf(red[0]);
    if (t == 0) g_logZ[r] = logZ;
    __syncthreads();

    // scalar, coalesced stores: consecutive threads -> consecutive addresses
    for (int e = t; e < ROWLEN; e += 256) {
        const int j  = e / KD;
        const int kk = e % KD;
        atten[base + (size_t)j * Q * KD + kk] = sv[e] - logZ;
    }
}

// One block (128 thr) per (i,q): logit/logit_m, conf softmax, argmax->hard,
// top-k of pseudo row (lowest-index tie break, like jax.lax.top_k),
// masked pseudo, loss numerator & phrase count.
__global__ void k_row(const float* __restrict__ outp,
                      const float* __restrict__ confid,
                      const unsigned char* __restrict__ xmask,
                      float* __restrict__ logit_m_o,
                      float* __restrict__ pseudo_o,
                      float* __restrict__ conf_o) {
    const int r = blockIdx.x;
    const int i = r / Q, qq = r % Q;
    const int t = threadIdx.x;           // 0..127
    __shared__ float slogit[KD];
    __shared__ float spseudo[KD];
    __shared__ unsigned char ssel[KD];
    __shared__ float rv[128];
    __shared__ int   ri[128];

    const float logZ = g_logZ[r];
    const int   bi   = g_bidx[i];
    const size_t diag = ((size_t)(i * B + i) * Q + qq) * KD;   // output diagonal
    const size_t rowo = ((size_t)i * Q + qq) * KD;             // (b,q,k) offset
    const size_t crow = ((size_t)bi * Q + qq) * KD;
    const int kk_top = g_topk;

    bool  m  = false;
    float lg = -FLT_MAX;
    float ps = 0.f;
    if (t < KD) {
        m = mask_at(xmask, rowo + t);
        const float l = outp[diag + t] / TEMP - logZ;
        slogit[t] = l;
        lg = m ? l : -FLT_MAX;
        logit_m_o[rowo + t] = lg;
        ps = m ? confid[crow + t] : 0.f;
        spseudo[t] = ps;
        ssel[t] = 0;
    }
    __syncthreads();

    // iterative top-k (k small); tie -> lower index
    for (int it = 0; it < kk_top; ++it) {
        float v = (t < KD && !ssel[t]) ? spseudo[t] : -FLT_MAX;
        rv[t] = v; ri[t] = t;
        __syncthreads();
        for (int s = 64; s > 0; s >>= 1) {
            if (t < s) {
                if (rv[t+s] > rv[t] || (rv[t+s] == rv[t] && ri[t+s] < ri[t])) {
                    rv[t] = rv[t+s]; ri[t] = ri[t+s];
                }
            }
            __syncthreads();
        }
        if (t == 0) ssel[ri[0]] = 1;
        __syncthreads();
    }

    // masked pseudo + loss numerator
    float contrib = 0.f;
    bool  sel = false;
    if (t < KD) {
        sel = (ssel[t] != 0) && m;
        const float pv = sel ? ps : 0.f;
        pseudo_o[rowo + t] = pv;
        contrib = -pv * slogit[t];
    }
    rv[t] = contrib; __syncthreads();
    for (int s = 64; s > 0; s >>= 1) { if (t < s) rv[t] += rv[t+s]; __syncthreads(); }
    if (t == 0) {
        atomicAdd(&g_loss_num, rv[0]);
        // phrase_mask = mask[:,:,0]; thread 0 holds kk==0
        atomicAdd(&g_phrase_cnt, sel ? 1.f : 0.f);
    }
    __syncthreads();

    // conf = softmax(logit_m) over k, then zero where masked
    rv[t] = lg; __syncthreads();
    for (int s = 64; s > 0; s >>= 1) { if (t < s) rv[t] = fmaxf(rv[t], rv[t+s]); __syncthreads(); }
    const float mmax = rv[0]; __syncthreads();
    float ev = (t < KD) ? expf(lg - mmax) : 0.f;
    rv[t] = ev; __syncthreads();
    for (int s = 64; s > 0; s >>= 1) { if (t < s) rv[t] += rv[t+s]; __syncthreads(); }
    const float denom = rv[0]; __syncthreads();
    float cv = 0.f;
    if (t < KD) {
        cv = m ? (ev / denom) : 0.f;
        conf_o[rowo + t] = cv;
    }
    // argmax(conf), tie -> lower index
    rv[t] = (t < KD) ? cv : -FLT_MAX; ri[t] = t;
    __syncthreads();
    for (int s = 64; s > 0; s >>= 1) {
        if (t < s) {
            if (rv[t+s] > rv[t] || (rv[t+s] == rv[t] && ri[t+s] < ri[t])) {
                rv[t] = rv[t+s]; ri[t] = ri[t+s];
            }
        }
        __syncthreads();
    }
    if (t == 0) g_harg[r] = ri[0];
}

// Rewrite the 64 updated rows of new_confidence (after bulk copy).
// Last occurrence of a duplicated batch_index wins (scatter order semantics).
__global__ void k_update(const float* __restrict__ confid,
                         const unsigned char* __restrict__ xmask,
                         float* __restrict__ newc) {
    const int i  = blockIdx.x;
    const int my = g_bidx[i];
    for (int j = i + 1; j < B; ++j) if (g_bidx[j] == my) return;  // not last -> skip
    for (int e = threadIdx.x; e < Q * KD; e += blockDim.x) {
        const int qq = e / KD, kk = e % KD;
        const int r  = i * Q + qq;
        const float h = (kk == g_harg[r] && mask_at(xmask, (size_t)i * Q * KD + e)) ? 1.f : 0.f;
        const size_t o = (size_t)my * Q * KD + e;
        newc[o] = EMA * confid[o] + (1.f - EMA) * h;
    }
}

__global__ void k_final(float* __restrict__ out) {
    out[0] = (g_loss_num / (g_phrase_cnt + 1.1920929e-07f)) * 1.0f; // BASE_TEMPERATURE=1
}

extern "C" void kernel_launch(void* const* d_in, const int* in_sizes, int n_in,
                              void* d_out, int out_size) {
    // Bind inputs by element count (all sizes distinct) -> order-proof.
    const float* outp = nullptr;
    const float* confid = nullptr;
    const int*   braw = nullptr;
    const unsigned char* xmask = nullptr;
    const int*   topkp = nullptr;
    for (int idx = 0; idx < n_in; ++idx) {
        const size_t sz = (size_t)in_sizes[idx];
        if      (sz == N_OUT)  outp   = (const float*)d_in[idx];
        else if (sz == N_CONF) confid = (const float*)d_in[idx];
        else if (sz == (size_t)B) braw = (const int*)d_in[idx];
        else if (sz == N_MASK) xmask  = (const unsigned char*)d_in[idx];
        else if (sz == 1)      topkp  = (const int*)d_in[idx];
    }
    float* out = (float*)d_out;

    const size_t ATT = 1;
    const size_t LOG = ATT + N_OUT;
    const size_t PSE = LOG + N_MASK;
    const size_t CNF = PSE + N_MASK;
    const size_t NEW = CNF + N_MASK;

    k_init<<<1, 1>>>(xmask, braw, topkp, topkp ? 1 : 0);
    k_softmax<<<BQ, 256>>>(outp, out + ATT);
    k_row<<<BQ, 128>>>(outp, confid, xmask, out + LOG, out + PSE, out + CNF);
    cudaMemcpyAsync(out + NEW, confid, N_CONF * sizeof(float),
                    cudaMemcpyDeviceToDevice);
    k_update<<<B, 256>>>(confid, xmask, out + NEW);
    k_final<<<1, 1>>>(out);
}

// round 5
// speedup vs baseline: 1.8098x; 1.8098x over previous
#include <cuda_runtime.h>
#include <cstdint>
#include <float.h>
#include <math.h>

#define B   64
#define Q   32
#define KD  100
#define BQ  (B*Q)              // 2048 rows (i,q)
#define ROWLEN  (B*KD)         // 6400 elems per softmax row
#define ROWLEN4 (ROWLEN/4)     // 1600 float4
#define TEMP 0.07f
#define EMA  0.99f

#define N_OUT   ((size_t)B*B*Q*KD)   // 13107200
#define N_CONF  ((size_t)30000*Q*KD) // 96000000
#define N_MASK  ((size_t)B*Q*KD)     // 204800

__device__ int   g_harg[BQ];
__device__ int   g_bidx[B];
__device__ int   g_mask_w;   // 1=u8, 4=i32, 8=i64, 5=f32, 9=f64
__device__ int   g_topk;
__device__ float g_loss_num;
__device__ float g_phrase_cnt;

__device__ __forceinline__ bool mask_at(const unsigned char* xm, size_t idx) {
    const int w = g_mask_w;
    if (w == 1) return xm[idx] != 0;
    if (w == 4) return ((const int*)xm)[idx] != 0;
    if (w == 8) return ((const long long*)xm)[idx] != 0;
    if (w == 5) return ((const float*)xm)[idx] != 0.f;
    return ((const double*)xm)[idx] != 0.0;
}

// One-warp setup: accumulator reset + dtype-width detection (parallel probes).
__global__ void k_init(const unsigned char* __restrict__ xm,
                       const int* __restrict__ braw,
                       const int* __restrict__ traw, int has_topk) {
    const int lane = threadIdx.x;   // 32 threads
    if (lane == 0) { g_loss_num = 0.f; g_phrase_cnt = 0.f; }

    // ---- x_mask width: cooperative probe of first 256 logical elements ----
    bool v8 = true, v4 = true, vf = true, vd = true;
    for (int e = lane; e < 256; e += 32) {
        const unsigned char* p = xm + 8*e;
        if (p[0] > 1) v8 = false;
        #pragma unroll
        for (int j = 1; j < 8; ++j) if (p[j] != 0) v8 = false;
        const unsigned char* q = xm + 4*e;
        if (q[0] > 1 || q[1] != 0 || q[2] != 0 || q[3] != 0) v4 = false;
        float  f = ((const float*)xm)[e];
        if (f != 0.f && f != 1.f) vf = false;
        double d = ((const double*)xm)[e];
        if (d != 0.0 && d != 1.0) vd = false;
    }
    const bool ok8 = __all_sync(0xffffffffu, v8);
    const bool ok4 = __all_sync(0xffffffffu, v4);
    const bool okd = __all_sync(0xffffffffu, vd);
    const bool okf = __all_sync(0xffffffffu, vf);
    if (lane == 0) {
        g_mask_w = ok8 ? 8 : (ok4 ? 4 : (okd ? 9 : (okf ? 5 : 1)));
    }

    // ---- batch_index dtype (uniform decision, parallel write) ----
    bool b64 = true, b32 = true, bf = true;
    for (int i = lane; i < B; i += 32) {
        if (i < 32) {   // i64 probe stays within first 256 bytes
            if (braw[2*i+1] != 0 || braw[2*i] < 0 || braw[2*i] >= 30000) b64 = false;
        }
        if (braw[i] < 0 || braw[i] >= 30000) b32 = false;
        float f = ((const float*)braw)[i];
        if (!(f >= 0.f && f < 30000.f) || f != floorf(f)) bf = false;
    }
    const bool ok64 = __all_sync(0xffffffffu, b64);
    const bool ok32 = __all_sync(0xffffffffu, b32);
    const bool okbf = __all_sync(0xffffffffu, bf);
    for (int i = lane; i < B; i += 32) {
        int v;
        if (ok64)      v = (int)((const long long*)braw)[i];
        else if (ok32) v = braw[i];
        else if (okbf) v = (int)((const float*)braw)[i];
        else           v = (int)((const double*)braw)[i];
        g_bidx[i] = v;
    }

    // ---- topk value ----
    if (lane == 0) {
        int v = 3;
        if (has_topk) {
            int vi = traw[0];                       // i32 or i64 low word
            if (vi >= 1 && vi <= KD) v = vi;
            else {
                float vfv = ((const float*)traw)[0];
                if (vfv >= 1.f && vfv <= (float)KD) v = (int)vfv;
                else {
                    double vd2 = ((const double*)traw)[0];
                    if (vd2 >= 1.0 && vd2 <= (double)KD) v = (int)vd2;
                }
            }
        }
        if (v > KD) v = KD;
        if (v < 0)  v = 0;
        g_topk = v;
    }
}

// Fused: per-(i,q) softmax over the 6400-elem slice (smem resident, __expf),
// atten store, diagonal logit + logit_m + pseudo/top-k + conf/argmax + loss
// accumulation, AND a grid-strided slice of the confidence->new_confidence
// bulk copy (overlaps DRAM copy with MUFU-heavy softmax across blocks).
__global__ void __launch_bounds__(256) k_main(
        const float* __restrict__ outp,
        const float* __restrict__ confid,
        const unsigned char* __restrict__ xmask,
        float* __restrict__ atten,
        float* __restrict__ logit_m_o,
        float* __restrict__ pseudo_o,
        float* __restrict__ conf_o,
        float* __restrict__ newc) {
    const int r = blockIdx.x;            // 0..2047
    const int i = r / Q, qq = r % Q;
    const int t = threadIdx.x;           // 0..255
    __shared__ float sv[ROWLEN];
    __shared__ float red[256];
    __shared__ int   ri[256];
    __shared__ float spseudo[KD];
    __shared__ unsigned char ssel[KD];
    const size_t base = (size_t)i * B * Q * KD + (size_t)qq * KD;

    // ---- load + scale + max ----
    float mx = -FLT_MAX;
    for (int f = t; f < ROWLEN4; f += 256) {
        const int e  = 4 * f;
        const int j  = e / KD;
        const int kk = e % KD;          // KD%4==0 -> all 4 lanes same j, contiguous
        float4 v = *(const float4*)(outp + base + (size_t)j * Q * KD + kk);
        v.x *= (1.f/TEMP); v.y *= (1.f/TEMP); v.z *= (1.f/TEMP); v.w *= (1.f/TEMP);
        *(float4*)(sv + e) = v;
        mx = fmaxf(mx, fmaxf(fmaxf(v.x, v.y), fmaxf(v.z, v.w)));
    }
    red[t] = mx; __syncthreads();
    for (int s = 128; s > 0; s >>= 1) { if (t < s) red[t] = fmaxf(red[t], red[t+s]); __syncthreads(); }
    mx = red[0]; __syncthreads();

    // ---- exp-sum (fast intrinsics) ----
    float sum = 0.f;
    for (int e = t; e < ROWLEN; e += 256) sum += __expf(sv[e] - mx);
    red[t] = sum; __syncthreads();
    for (int s = 128; s > 0; s >>= 1) { if (t < s) red[t] += red[t+s]; __syncthreads(); }
    const float logZ = mx + __logf(red[0]);
    __syncthreads();

    // ---- atten store (scalar, coalesced; atten base is 4B-aligned only) ----
    for (int e = t; e < ROWLEN; e += 256) {
        const int j  = e / KD;
        const int kk = e % KD;
        atten[base + (size_t)j * Q * KD + kk] = sv[e] - logZ;
    }

    // ---- per-row work: diagonal slice already in smem at sv[i*KD + k] ----
    const int   bi   = g_bidx[i];
    const size_t rowo = ((size_t)i * Q + qq) * KD;
    const size_t crow = ((size_t)bi * Q + qq) * KD;
    const int kk_top = g_topk;

    bool  m  = false;
    float lg = -FLT_MAX;
    float ps = 0.f;
    float lgt = 0.f;     // unmasked logit for loss
    if (t < KD) {
        m   = mask_at(xmask, rowo + t);
        lgt = sv[i*KD + t] - logZ;
        lg  = m ? lgt : -FLT_MAX;
        logit_m_o[rowo + t] = lg;
        ps = m ? confid[crow + t] : 0.f;
        spseudo[t] = ps;
        ssel[t] = 0;
    }
    __syncthreads();

    // iterative top-k (k small); tie -> lower index (jax.lax.top_k order)
    for (int it = 0; it < kk_top; ++it) {
        float v = (t < KD && !ssel[t]) ? spseudo[t] : -FLT_MAX;
        red[t] = v; ri[t] = t;
        __syncthreads();
        for (int s = 128; s > 0; s >>= 1) {
            if (t < s) {
                if (red[t+s] > red[t] || (red[t+s] == red[t] && ri[t+s] < ri[t])) {
                    red[t] = red[t+s]; ri[t] = ri[t+s];
                }
            }
            __syncthreads();
        }
        if (t == 0) ssel[ri[0]] = 1;
        __syncthreads();
    }

    // masked pseudo + loss numerator + phrase mask count
    float contrib = 0.f;
    bool  sel = false;
    if (t < KD) {
        sel = (ssel[t] != 0) && m;
        const float pv = sel ? ps : 0.f;
        pseudo_o[rowo + t] = pv;
        contrib = -pv * lgt;
    }
    red[t] = contrib; __syncthreads();
    for (int s = 128; s > 0; s >>= 1) { if (t < s) red[t] += red[t+s]; __syncthreads(); }
    if (t == 0) {
        atomicAdd(&g_loss_num, red[0]);
        atomicAdd(&g_phrase_cnt, sel ? 1.f : 0.f);   // thread 0 holds k==0
    }
    __syncthreads();

    // conf = softmax(logit_m) over k, zero where masked; argmax -> g_harg
    red[t] = lg; __syncthreads();
    for (int s = 128; s > 0; s >>= 1) { if (t < s) red[t] = fmaxf(red[t], red[t+s]); __syncthreads(); }
    const float mmax = red[0]; __syncthreads();
    float ev = (t < KD && lg > -FLT_MAX) ? __expf(lg - mmax) : 0.f;
    red[t] = ev; __syncthreads();
    for (int s = 128; s > 0; s >>= 1) { if (t < s) red[t] += red[t+s]; __syncthreads(); }
    const float denom = red[0]; __syncthreads();
    if (t < KD) conf_o[rowo + t] = m ? (ev / denom) : 0.f;

    red[t] = (t < KD && m) ? ev : -FLT_MAX; ri[t] = t;
    __syncthreads();
    for (int s = 128; s > 0; s >>= 1) {
        if (t < s) {
            if (red[t+s] > red[t] || (red[t+s] == red[t] && ri[t+s] < ri[t])) {
                red[t] = red[t+s]; ri[t] = ri[t+s];
            }
        }
        __syncthreads();
    }
    if (t == 0) g_harg[r] = ri[0];

    // ---- bulk copy slice: confidence -> new_confidence (overlapped) ----
    for (size_t idx = (size_t)r * 256 + t; idx < N_CONF; idx += (size_t)BQ * 256)
        newc[idx] = confid[idx];
}

// Rewrite the 64 updated rows of new_confidence (after bulk copy).
// Last occurrence of a duplicated batch_index wins (scatter order semantics).
__global__ void k_update(const float* __restrict__ confid,
                         const unsigned char* __restrict__ xmask,
                         float* __restrict__ newc) {
    const int r = blockIdx.x;            // 0..2047
    const int i = r / Q, qq = r % Q;
    const int my = g_bidx[i];
    for (int j = i + 1; j < B; ++j) if (g_bidx[j] == my) return;  // not last -> skip
    const int t = threadIdx.x;           // 128
    if (t < KD) {
        const size_t mrow = ((size_t)i * Q + qq) * KD;
        const float h = (t == g_harg[r] && mask_at(xmask, mrow + t)) ? 1.f : 0.f;
        const size_t o = ((size_t)my * Q + qq) * KD + t;
        newc[o] = EMA * confid[o] + (1.f - EMA) * h;
    }
}

__global__ void k_final(float* __restrict__ out) {
    out[0] = (g_loss_num / (g_phrase_cnt + 1.1920929e-07f)) * 1.0f; // BASE_TEMPERATURE=1
}

extern "C" void kernel_launch(void* const* d_in, const int* in_sizes, int n_in,
                              void* d_out, int out_size) {
    // Bind inputs by element count (all sizes distinct) -> order-proof.
    const float* outp = nullptr;
    const float* confid = nullptr;
    const int*   braw = nullptr;
    const unsigned char* xmask = nullptr;
    const int*   topkp = nullptr;
    for (int idx = 0; idx < n_in; ++idx) {
        const size_t sz = (size_t)in_sizes[idx];
        if      (sz == N_OUT)  outp   = (const float*)d_in[idx];
        else if (sz == N_CONF) confid = (const float*)d_in[idx];
        else if (sz == (size_t)B) braw = (const int*)d_in[idx];
        else if (sz == N_MASK) xmask  = (const unsigned char*)d_in[idx];
        else if (sz == 1)      topkp  = (const int*)d_in[idx];
    }
    float* out = (float*)d_out;

    const size_t ATT = 1;
    const size_t LOG = ATT + N_OUT;
    const size_t PSE = LOG + N_MASK;
    const size_t CNF = PSE + N_MASK;
    const size_t NEW = CNF + N_MASK;

    k_init<<<1, 32>>>(xmask, braw, topkp, topkp ? 1 : 0);
    k_main<<<BQ, 256>>>(outp, confid, xmask,
                        out + ATT, out + LOG, out + PSE, out + CNF, out + NEW);
    k_update<<<BQ, 128>>>(confid, xmask, out + NEW);
    k_final<<<1, 1>>>(out);
}